// round 16
// baseline (speedup 1.0000x reference)
#include <cuda_runtime.h>
#include <cuda_bf16.h>

// SmoothnessLoss: loss = mean_i( (sHat_i - sY_i)^2 ), i in [0, W), W = N-k-1
// s_i = sum_{j<k} | x[i+j] - mean_j |, k = 64.
// Pair identity: |a-m|+|b-m| = max(|a-b|, |(a+b)-2m|).
// R13 structure + (1) packed f32x2 't' computation in pass 2 (5 slots per
// 2 pair-windows instead of 6) and (2) warp-uniform pairing parity (no
// duplicated construction paths).

#define K_WIN 64
#define BLOCK 256
#define WPT 8
#define SPAN 16                               // window span per upos
#define STRIDE ((BLOCK / 2) * SPAN)           // 2048 windows per block-iter
#define GRID 296                              // 2 blocks/SM x 148 SMs

typedef unsigned long long u64;

__device__ float g_partials[GRID];
__device__ unsigned int g_count = 0;

__device__ __forceinline__ u64 addx2(u64 a, u64 b) {
    u64 r; asm("add.rn.f32x2 %0, %1, %2;" : "=l"(r) : "l"(a), "l"(b)); return r;
}
__device__ __forceinline__ u64 pk(float lo, float hi) {
    u64 r; asm("mov.b64 %0, {%1, %2};" : "=l"(r) : "f"(lo), "f"(hi)); return r;
}
__device__ __forceinline__ void upk(u64 p, float& lo, float& hi) {
    asm("mov.b64 {%0, %1}, %2;" : "=f"(lo), "=f"(hi) : "l"(p));
}

// 8 windows (spacing 2) over elements [eb, eb+80).
// PAR=0: pair p = (e[2p], e[2p+1]);  PAR=1: pair p = (e[2p+1], e[2p+2]).
// Local window j covers pairs [j, j+31]. Pairs 0..38 are needed.
template <int PAR>
__device__ __forceinline__ void seg8(const float4* __restrict__ f4, float a[WPT])
{
    u64   s2[19];     // packed pair sums: s2[i] = (sv[2i], sv[2i+1])
    float sv[39];     // scalar pair sums (aliases of s2 halves after packing)
    float d[39];      // pair differences

    if (PAR == 0) {
        #pragma unroll
        for (int q = 0; q < 20; q++) {
            float4 c = f4[q];
            sv[2*q] = c.x + c.y;  d[2*q] = c.x - c.y;
            if (2*q + 1 <= 38) { sv[2*q+1] = c.z + c.w;  d[2*q+1] = c.z - c.w; }
            if (q < 19) s2[q] = pk(sv[2*q], sv[2*q+1]);
        }
    } else {
        float4 cp = f4[0];
        sv[0] = cp.y + cp.z;  d[0] = cp.y - cp.z;
        float pw = cp.w;
        #pragma unroll
        for (int q = 1; q < 20; q++) {
            float4 c = f4[q];
            sv[2*q-1] = pw + c.x;   d[2*q-1] = pw - c.x;
            if (2*q <= 38) { sv[2*q] = c.y + c.z;  d[2*q] = c.y - c.z; }
            pw = c.w;
            s2[q-1] = pk(sv[2*q-2], sv[2*q-1]);
        }
    }

    // Means: sw_0 = sum pairs 0..31 (chunks 0..15), then slide.
    u64 q0 = s2[0], q1 = s2[1], q2 = s2[2], q3 = s2[3];
    #pragma unroll
    for (int i = 1; i < 4; i++) {
        q0 = addx2(q0, s2[4*i]);
        q1 = addx2(q1, s2[4*i+1]);
        q2 = addx2(q2, s2[4*i+2]);
        q3 = addx2(q3, s2[4*i+3]);
    }
    float lo, hi; upk(addx2(addx2(q0, q1), addx2(q2, q3)), lo, hi);
    float sw = lo + hi;

    float twoM[WPT];
    #pragma unroll
    for (int j = 0; j < WPT; j++) {
        twoM[j] = sw * (1.0f / 32.0f);        // 2*mean (mean = sw/64)
        if (j < 7) sw += sv[j + 32] - sv[j];
    }

    // Pass 2: per window, packed t for aligned chunks, scalar boundary pairs.
    #pragma unroll
    for (int j = 0; j < WPT; j++) {
        const float tm = twoM[j];
        const u64 nm2 = pk(-tm, -tm);
        float acc0 = 0.0f, acc1 = 0.0f;
        if ((j & 1) == 0) {
            const int b = j >> 1;             // chunks b..b+15 = pairs j..j+31
            #pragma unroll
            for (int i = 0; i < 16; i++) {
                float t0, t1; upk(addx2(s2[b + i], nm2), t0, t1);
                acc0 += fmaxf(fabsf(d[2*(b+i)]),     fabsf(t0));
                acc1 += fmaxf(fabsf(d[2*(b+i) + 1]), fabsf(t1));
            }
        } else {
            const int b = (j + 1) >> 1;       // chunks b..b+14 = pairs j+1..j+30
            const float tf = sv[j] - tm;
            acc0 = fmaxf(fabsf(d[j]), fabsf(tf));
            #pragma unroll
            for (int i = 0; i < 15; i++) {
                float t0, t1; upk(addx2(s2[b + i], nm2), t0, t1);
                acc0 += fmaxf(fabsf(d[2*(b+i)]),     fabsf(t0));
                acc1 += fmaxf(fabsf(d[2*(b+i) + 1]), fabsf(t1));
            }
            const float tl = sv[j + 31] - tm;
            acc1 += fmaxf(fabsf(d[j + 31]), fabsf(tl));
        }
        a[j] = acc0 + acc1;
    }
}

// Tail fallback: one window, elements p[0..63] (in-bounds for all w < W).
__device__ float window_scalar(const float* __restrict__ p)
{
    float s0 = 0.f, s1 = 0.f, s2 = 0.f, s3 = 0.f;
    #pragma unroll 1
    for (int i = 0; i < K_WIN; i += 4) {
        s0 += p[i]; s1 += p[i+1]; s2 += p[i+2]; s3 += p[i+3];
    }
    const float m = ((s0 + s1) + (s2 + s3)) * (1.0f / (float)K_WIN);
    float t0 = 0.f, t1 = 0.f;
    #pragma unroll 1
    for (int i = 0; i < K_WIN; i += 2) {
        t0 += fabsf(p[i]   - m);
        t1 += fabsf(p[i+1] - m);
    }
    return t0 + t1;
}

__global__ void __launch_bounds__(BLOCK, 2)
smoothness_persist_kernel(const float* __restrict__ yh,
                          const float* __restrict__ yy,
                          int W, int N, int WB,
                          float* __restrict__ out, double invW)
{
    __shared__ float  redf[BLOCK / 32];
    __shared__ double redd[BLOCK / 32];
    __shared__ int    amLast;

    const int tid  = threadIdx.x;
    const int wid  = tid >> 5;
    const int lane = tid & 31;
    const int par  = wid & 1;                      // warp-uniform parity
    const int upos = ((wid >> 1) << 5) | lane;     // 0..127
    const int wstart = blockIdx.x * WB;            // multiple of 16
    const int wend   = min(wstart + WB, W);

    float d2 = 0.0f;

    #pragma unroll 1
    for (int g0 = wstart; g0 < wend; g0 += STRIDE) {
        const int eb = g0 + SPAN * upos;           // float4-aligned element base
        const int w0 = eb + par;                   // first window of this thread
        if (w0 >= wend) continue;

        float a1[WPT], a2[WPT];
        if (eb + 80 <= N) {
            if (par == 0) {
                seg8<0>(reinterpret_cast<const float4*>(yh + eb), a1);
                seg8<0>(reinterpret_cast<const float4*>(yy + eb), a2);
            } else {
                seg8<1>(reinterpret_cast<const float4*>(yh + eb), a1);
                seg8<1>(reinterpret_cast<const float4*>(yy + eb), a2);
            }
        } else {
            #pragma unroll 1
            for (int j = 0; j < WPT; j++) {
                const int w = w0 + 2 * j;
                if (w < wend) {
                    a1[j] = window_scalar(yh + w);
                    a2[j] = window_scalar(yy + w);
                } else { a1[j] = 0.0f; a2[j] = 0.0f; }
            }
        }

        #pragma unroll
        for (int j = 0; j < WPT; j++) {
            if (w0 + 2 * j < wend) {
                const float dd = a1[j] - a2[j];
                d2 += dd * dd;
            }
        }
    }

    // Block reduction of d2.
    #pragma unroll
    for (int off = 16; off > 0; off >>= 1)
        d2 += __shfl_down_sync(0xffffffffu, d2, off);

    if (lane == 0) redf[wid] = d2;
    __syncthreads();
    if (wid == 0) {
        float vv = (lane < BLOCK / 32) ? redf[lane] : 0.0f;
        #pragma unroll
        for (int off = 4; off > 0; off >>= 1)
            vv += __shfl_down_sync(0xffffffffu, vv, off);
        if (lane == 0) {
            g_partials[blockIdx.x] = vv;
            __threadfence();
            unsigned int c = atomicAdd(&g_count, 1u);
            amLast = (c == (unsigned int)(gridDim.x - 1));
        }
    }
    __syncthreads();

    if (amLast) {
        // Deterministic final reduction (fixed order/topology).
        double sd = 0.0;
        #pragma unroll 1
        for (int i = tid; i < GRID; i += BLOCK)
            sd += (double)g_partials[i];
        #pragma unroll
        for (int off = 16; off > 0; off >>= 1)
            sd += __shfl_down_sync(0xffffffffu, sd, off);
        if (lane == 0) redd[wid] = sd;
        __syncthreads();
        if (wid == 0) {
            double vv = (lane < BLOCK / 32) ? redd[lane] : 0.0;
            #pragma unroll
            for (int off = 4; off > 0; off >>= 1)
                vv += __shfl_down_sync(0xffffffffu, vv, off);
            if (lane == 0) {
                out[0] = (float)(vv * invW);
                g_count = 0;                 // reset for next graph replay
            }
        }
    }
}

extern "C" void kernel_launch(void* const* d_in, const int* in_sizes, int n_in,
                              void* d_out, int out_size)
{
    const float* yh = (const float*)d_in[0];
    const float* yy = (const float*)d_in[1];
    const int N = in_sizes[0];
    const int W = N - K_WIN - 1;
    int WB = (W + GRID - 1) / GRID;
    WB = (WB + 15) & ~15;                        // multiple of 16 (SPAN/alignment)

    smoothness_persist_kernel<<<GRID, BLOCK>>>(yh, yy, W, N, WB,
                                               (float*)d_out, 1.0 / (double)W);
}

// round 17
// speedup vs baseline: 1.3963x; 1.3963x over previous
#include <cuda_runtime.h>
#include <cuda_bf16.h>

// SmoothnessLoss: loss = mean_i( (sHat_i - sY_i)^2 ), i in [0, W), W = N-k-1
// s_i = sum_{j<k} | x[i+j] - mean_j |, k = 64.
// Pair identity: |a-m|+|b-m| = max(|a-b|, |(a+b)-2m|). R13 structure exactly,
// but pairing parity is WARP-UNIFORM (template) so no intra-warp dual-path
// construction. Windows spaced 2 per thread => every window = 32 pairs.

#define K_WIN 64
#define BLOCK 256
#define WPT 8
#define SPAN 16                               // window span per upos
#define STRIDE ((BLOCK / 2) * SPAN)           // 2048 windows per block-iter
#define GRID 296                              // 2 blocks/SM x 148 SMs

__device__ float g_partials[GRID];
__device__ unsigned int g_count = 0;

// 8 windows (spacing 2) over elements [eb, eb+80). PAR selects the pairing:
// PAR=0: pair p = (e[2p], e[2p+1]);  PAR=1: pair p = (e[2p+1], e[2p+2]).
// Local window j (j=0..7) = pairs [j, j+32).  Pairs p = 0..38.
template <int PAR>
__device__ __forceinline__ void seg8_pairs(const float4* __restrict__ f4,
                                           float a[WPT])
{
    float4 F[20];
    #pragma unroll
    for (int q = 0; q < 20; q++) F[q] = f4[q];

    float s[39], d[39];
    if (PAR == 0) {
        #pragma unroll
        for (int q = 0; q < 20; q++) {
            if (2 * q < 39)     { s[2*q]   = F[q].x + F[q].y; d[2*q]   = F[q].x - F[q].y; }
            if (2 * q + 1 < 39) { s[2*q+1] = F[q].z + F[q].w; d[2*q+1] = F[q].z - F[q].w; }
        }
    } else {
        #pragma unroll
        for (int q = 0; q < 20; q++) {
            if (2 * q < 39)     { s[2*q]   = F[q].y + F[q].z;   d[2*q]   = F[q].y - F[q].z; }
            if (2 * q + 1 < 39) { s[2*q+1] = F[q].w + F[q+1].x; d[2*q+1] = F[q].w - F[q+1].x; }
        }
    }

    // Window sums from pair sums: sw(0) = sum s[0..31], slide by one pair.
    float q0 = s[0], q1 = s[1], q2 = s[2], q3 = s[3];
    #pragma unroll
    for (int p = 1; p < 8; p++) {
        q0 += s[4*p];
        q1 += s[4*p+1];
        q2 += s[4*p+2];
        q3 += s[4*p+3];
    }
    float sw = (q0 + q1) + (q2 + q3);

    float twoM[WPT];
    #pragma unroll
    for (int j = 0; j < WPT; j++) {
        twoM[j] = sw * (1.0f / 32.0f);        // 2 * mean  (mean = sw/64)
        sw += s[j + 32] - s[j];
    }

    // Pass 2: per window, 32 pairs, 3 instrs each (FADD, FMNMX|.|, FADD).
    #pragma unroll
    for (int j = 0; j < WPT; j++) {
        const float tm = twoM[j];
        float acc0 = 0.0f, acc1 = 0.0f;
        #pragma unroll
        for (int p = j; p < j + 32; p += 2) {
            float t0 = s[p]     - tm;
            float t1 = s[p + 1] - tm;
            acc0 += fmaxf(fabsf(d[p]),     fabsf(t0));
            acc1 += fmaxf(fabsf(d[p + 1]), fabsf(t1));
        }
        a[j] = acc0 + acc1;
    }
}

// Tail fallback: one window, elements p[0..63] (in-bounds for all w < W).
__device__ float window_scalar(const float* __restrict__ p)
{
    float s0 = 0.f, s1 = 0.f, s2 = 0.f, s3 = 0.f;
    #pragma unroll 1
    for (int i = 0; i < K_WIN; i += 4) {
        s0 += p[i]; s1 += p[i+1]; s2 += p[i+2]; s3 += p[i+3];
    }
    const float m = ((s0 + s1) + (s2 + s3)) * (1.0f / (float)K_WIN);
    float t0 = 0.f, t1 = 0.f;
    #pragma unroll 1
    for (int i = 0; i < K_WIN; i += 2) {
        t0 += fabsf(p[i]   - m);
        t1 += fabsf(p[i+1] - m);
    }
    return t0 + t1;
}

__global__ void __launch_bounds__(BLOCK, 2)
smoothness_persist_kernel(const float* __restrict__ yh,
                          const float* __restrict__ yy,
                          int W, int N, int WB,
                          float* __restrict__ out, double invW)
{
    __shared__ float  redf[BLOCK / 32];
    __shared__ double redd[BLOCK / 32];
    __shared__ int    amLast;

    const int tid  = threadIdx.x;
    const int wid  = tid >> 5;
    const int lane = tid & 31;
    const int par  = wid & 1;                      // warp-uniform parity
    const int upos = ((wid >> 1) << 5) | lane;     // 0..127
    const int wstart = blockIdx.x * WB;            // multiple of 16
    const int wend   = min(wstart + WB, W);

    float d2 = 0.0f;

    #pragma unroll 1
    for (int g0 = wstart; g0 < wend; g0 += STRIDE) {
        const int eb = g0 + SPAN * upos;           // float4-aligned element base
        const int w0 = eb + par;                   // first window of this thread
        if (w0 >= wend) continue;

        float a1[WPT], a2[WPT];
        if (eb + 80 <= N) {
            if (par == 0) {
                seg8_pairs<0>(reinterpret_cast<const float4*>(yh + eb), a1);
                seg8_pairs<0>(reinterpret_cast<const float4*>(yy + eb), a2);
            } else {
                seg8_pairs<1>(reinterpret_cast<const float4*>(yh + eb), a1);
                seg8_pairs<1>(reinterpret_cast<const float4*>(yy + eb), a2);
            }
        } else {
            #pragma unroll 1
            for (int j = 0; j < WPT; j++) {
                const int w = w0 + 2 * j;
                if (w < wend) {
                    a1[j] = window_scalar(yh + w);
                    a2[j] = window_scalar(yy + w);
                } else { a1[j] = 0.0f; a2[j] = 0.0f; }
            }
        }

        #pragma unroll
        for (int j = 0; j < WPT; j++) {
            if (w0 + 2 * j < wend) {
                const float dd = a1[j] - a2[j];
                d2 += dd * dd;
            }
        }
    }

    // Block reduction of d2.
    #pragma unroll
    for (int off = 16; off > 0; off >>= 1)
        d2 += __shfl_down_sync(0xffffffffu, d2, off);

    if (lane == 0) redf[wid] = d2;
    __syncthreads();
    if (wid == 0) {
        float vv = (lane < BLOCK / 32) ? redf[lane] : 0.0f;
        #pragma unroll
        for (int off = 4; off > 0; off >>= 1)
            vv += __shfl_down_sync(0xffffffffu, vv, off);
        if (lane == 0) {
            g_partials[blockIdx.x] = vv;
            __threadfence();
            unsigned int c = atomicAdd(&g_count, 1u);
            amLast = (c == (unsigned int)(gridDim.x - 1));
        }
    }
    __syncthreads();

    if (amLast) {
        // Deterministic final reduction (fixed order/topology).
        double sd = 0.0;
        #pragma unroll 1
        for (int i = tid; i < GRID; i += BLOCK)
            sd += (double)g_partials[i];
        #pragma unroll
        for (int off = 16; off > 0; off >>= 1)
            sd += __shfl_down_sync(0xffffffffu, sd, off);
        if (lane == 0) redd[wid] = sd;
        __syncthreads();
        if (wid == 0) {
            double vv = (lane < BLOCK / 32) ? redd[lane] : 0.0;
            #pragma unroll
            for (int off = 4; off > 0; off >>= 1)
                vv += __shfl_down_sync(0xffffffffu, vv, off);
            if (lane == 0) {
                out[0] = (float)(vv * invW);
                g_count = 0;                 // reset for next graph replay
            }
        }
    }
}

extern "C" void kernel_launch(void* const* d_in, const int* in_sizes, int n_in,
                              void* d_out, int out_size)
{
    const float* yh = (const float*)d_in[0];
    const float* yy = (const float*)d_in[1];
    const int N = in_sizes[0];
    const int W = N - K_WIN - 1;
    int WB = (W + GRID - 1) / GRID;
    WB = (WB + 15) & ~15;                        // multiple of 16 (SPAN/alignment)

    smoothness_persist_kernel<<<GRID, BLOCK>>>(yh, yy, W, N, WB,
                                               (float*)d_out, 1.0 / (double)W);
}